// round 2
// baseline (speedup 1.0000x reference)
#include <cuda_runtime.h>
#include <math.h>

// ---------------- problem constants / tiling ----------------
#define BM 128
#define BN 64
#define BK 32
#define TM 8
#define TN 4

#define MAX_B 512
#define MAX_D 512
#define MAX_C 100000
#define NCBLK_MAX ((MAX_C + BN - 1) / BN)   // 1563

// ArcFace constants (margin=0.5, scale=64, t=0.2)
#define ARC_COS_M 0.8775825618903728f
#define ARC_SIN_M 0.479425538604203f
#define ARC_TH   (-0.8775825618903728f)
#define ARC_MM    0.2397127693021015f
#define ARC_EPS   1e-7f
#define ARC_SCALE 64.0f
#define ARC_T     0.2f

// ---------------- static scratch (no allocations allowed) ----------------
__device__ float  g_en[MAX_B * MAX_D];          // normalized embeddings
__device__ float  g_winv[MAX_C];                // 1/||w_c||
__device__ float  g_phi[MAX_B];                 // per-sample phi
__device__ int    g_gt[MAX_B];                  // gt as int32
__device__ float2 g_part[(size_t)MAX_B * NCBLK_MAX]; // per (sample, c-block) (max, sumexp)
__device__ float  g_samp[MAX_B];                // per-sample (lse - s*phi)
__device__ int    g_gt_is_i32;                  // dtype probe result

// ---------------- K0: probe gt dtype (int64 vs int32) ----------------
// If the buffer really holds int64 class indices, every value is in [0, C).
// If it holds int32, reading as int64 packs two labels -> almost surely
// produces a value >= C (high word nonzero). Deterministic, no host sync.
__global__ void k_probe(const void* __restrict__ gt, int B, int C) {
    const long long* p = (const long long*)gt;
    int t = threadIdx.x;
    int bad = 0;
    for (int i = t; i < B; i += 256) {
        long long v = p[i];
        if (v < 0 || v >= (long long)C) bad = 1;
    }
    __shared__ int sh[256];
    sh[t] = bad;
    __syncthreads();
    for (int o = 128; o > 0; o >>= 1) {
        if (t < o) sh[t] |= sh[t + o];
        __syncthreads();
    }
    if (t == 0) g_gt_is_i32 = sh[0];
}

// ---------------- K1: normalize embedding rows ----------------
__global__ void k_norm_e(const float* __restrict__ e, int D) {
    int b = blockIdx.x;
    int t = threadIdx.x;
    float ss = 0.f;
    for (int d = t; d < D; d += 256) {
        float v = e[(size_t)b * D + d];
        ss += v * v;
    }
    __shared__ float sh[256];
    sh[t] = ss;
    __syncthreads();
    for (int o = 128; o > 0; o >>= 1) {
        if (t < o) sh[t] += sh[t + o];
        __syncthreads();
    }
    float rn = rsqrtf(sh[0]);
    for (int d = t; d < D; d += 256)
        g_en[(size_t)b * D + d] = e[(size_t)b * D + d] * rn;
}

// ---------------- K2: weight row inverse norms (1 warp / row) ----------------
__global__ void k_winv(const float* __restrict__ w, int C, int D) {
    int row = blockIdx.x * 8 + (threadIdx.x >> 5);
    if (row >= C) return;
    int lane = threadIdx.x & 31;
    const float* wr = w + (size_t)row * D;
    float ss = 0.f;
    for (int d = lane * 4; d < D; d += 128) {
        float4 v = *(const float4*)(wr + d);
        ss += v.x * v.x + v.y * v.y + v.z * v.z + v.w * v.w;
    }
    #pragma unroll
    for (int o = 16; o > 0; o >>= 1)
        ss += __shfl_xor_sync(0xffffffffu, ss, o);
    if (lane == 0) g_winv[row] = rsqrtf(ss);
}

// ---------------- K3: per-sample pos (gt cosine) and phi ----------------
__global__ void k_phi(const float* __restrict__ w, const void* __restrict__ gt,
                      int D, int C) {
    int b = blockIdx.x;
    int t = threadIdx.x;

    __shared__ int sg;
    if (t == 0) {
        long long v;
        if (g_gt_is_i32) v = (long long)((const int*)gt)[b];
        else             v = ((const long long*)gt)[b];
        if (v < 0) v = 0;
        if (v >= C) v = C - 1;          // clamp defensively; never OOB
        sg = (int)v;
    }
    __syncthreads();
    int g = sg;

    const float* er = g_en + (size_t)b * D;
    const float* wr = w + (size_t)g * D;
    float s = 0.f;
    for (int d = t; d < D; d += 256) s += er[d] * wr[d];
    __shared__ float sh[256];
    sh[t] = s;
    __syncthreads();
    for (int o = 128; o > 0; o >>= 1) {
        if (t < o) sh[t] += sh[t + o];
        __syncthreads();
    }
    if (t == 0) {
        float pos = sh[0] * g_winv[g];
        pos = fminf(fmaxf(pos, -1.f + ARC_EPS), 1.f - ARC_EPS);
        float s2 = 1.f - pos * pos;
        s2 = fminf(fmaxf(s2, ARC_EPS), 1.f - ARC_EPS);
        float sin_t = sqrtf(s2);
        float ph = pos * ARC_COS_M - sin_t * ARC_SIN_M;
        if (!(pos > ARC_TH)) ph = pos - ARC_MM;
        g_phi[b] = ph;
        g_gt[b] = g;
    }
}

// ---------------- K4: fused GEMM + margin transform + partial LSE ----------------
__global__ __launch_bounds__(256) void k_gemm(const float* __restrict__ w,
                                              int D, int C, int nCblk) {
    __shared__ __align__(16) float As[BK][BM + 4];
    __shared__ __align__(16) float Bs[BK][BN + 4];

    int t  = threadIdx.x;
    int tx = t & 15;     // 16 thread-cols  -> TN=4 classes each
    int ty = t >> 4;     // 16 thread-rows  -> TM=8 samples each
    int bm0 = blockIdx.y * BM;
    int cn0 = blockIdx.x * BN;

    float acc[TM][TN];
    #pragma unroll
    for (int i = 0; i < TM; i++)
        #pragma unroll
        for (int j = 0; j < TN; j++)
            acc[i][j] = 0.f;

    for (int k0 = 0; k0 < D; k0 += BK) {
        // A tile: 128 x 32 floats = 1024 float4 (4 per thread)
        #pragma unroll
        for (int v = 0; v < 4; v++) {
            int lin = t + v * 256;     // float4 index
            int row = lin >> 3;        // 8 float4 per row
            int c4  = lin & 7;
            float4 val = *(const float4*)(g_en + (size_t)(bm0 + row) * D + k0 + c4 * 4);
            As[c4 * 4 + 0][row] = val.x;
            As[c4 * 4 + 1][row] = val.y;
            As[c4 * 4 + 2][row] = val.z;
            As[c4 * 4 + 3][row] = val.w;
        }
        // B tile: 64 x 32 floats = 512 float4 (2 per thread), normalize on load
        #pragma unroll
        for (int v = 0; v < 2; v++) {
            int lin = t + v * 256;
            int row = lin >> 3;
            int c4  = lin & 7;
            int c   = cn0 + row;
            float4 val = make_float4(0.f, 0.f, 0.f, 0.f);
            float wi = 0.f;
            if (c < C) {
                val = *(const float4*)(w + (size_t)c * D + k0 + c4 * 4);
                wi = g_winv[c];
            }
            Bs[c4 * 4 + 0][row] = val.x * wi;
            Bs[c4 * 4 + 1][row] = val.y * wi;
            Bs[c4 * 4 + 2][row] = val.z * wi;
            Bs[c4 * 4 + 3][row] = val.w * wi;
        }
        __syncthreads();

        #pragma unroll
        for (int k = 0; k < BK; k++) {
            float4 a0 = *(const float4*)&As[k][ty * TM];
            float4 a1 = *(const float4*)&As[k][ty * TM + 4];
            float4 b0 = *(const float4*)&Bs[k][tx * TN];
            float a[TM] = {a0.x, a0.y, a0.z, a0.w, a1.x, a1.y, a1.z, a1.w};
            float bb[TN] = {b0.x, b0.y, b0.z, b0.w};
            #pragma unroll
            for (int i = 0; i < TM; i++)
                #pragma unroll
                for (int j = 0; j < TN; j++)
                    acc[i][j] = fmaf(a[i], bb[j], acc[i][j]);
        }
        __syncthreads();
    }

    // Epilogue: margin transform + per-sample (over this block's 64 classes)
    // online max/sumexp, reduced across the 16 lanes sharing a sample.
    const float HI = 1.f - ARC_EPS, LO = -1.f + ARC_EPS;
    #pragma unroll
    for (int i = 0; i < TM; i++) {
        int b = bm0 + ty * TM + i;
        float ph = g_phi[b];
        int g = g_gt[b];
        float vals[TN];
        float m = -1e30f;
        #pragma unroll
        for (int j = 0; j < TN; j++) {
            int c = cn0 + tx * TN + j;
            float v;
            if (c < C) {
                float cv = fminf(fmaxf(acc[i][j], LO), HI);
                v = (cv > ph) ? fmaf(ARC_T + 1.f, cv, ARC_T) : cv;
                if (c == g) v = ph;
                v *= ARC_SCALE;
            } else {
                v = -1e30f;   // excluded class -> exp() == 0
            }
            vals[j] = v;
            m = fmaxf(m, v);
        }
        // reduce across the 16 lanes of this thread-row (lane bits 0..3)
        #pragma unroll
        for (int o = 1; o < 16; o <<= 1)
            m = fmaxf(m, __shfl_xor_sync(0xffffffffu, m, o));
        float s = 0.f;
        #pragma unroll
        for (int j = 0; j < TN; j++)
            s += __expf(vals[j] - m);   // exp(-huge) == 0 for padded classes
        #pragma unroll
        for (int o = 1; o < 16; o <<= 1)
            s += __shfl_xor_sync(0xffffffffu, s, o);
        if (tx == 0)
            g_part[(size_t)b * nCblk + blockIdx.x] = make_float2(m, s);
    }
}

// ---------------- K5: per-sample logsumexp combine ----------------
__global__ void k_lse(int nCblk) {
    int b = blockIdx.x;
    int t = threadIdx.x;
    const float2* p = g_part + (size_t)b * nCblk;
    float m = -1e30f, s = 0.f;
    for (int i = t; i < nCblk; i += 256) {
        float2 q = p[i];
        if (q.x > m) { s = s * __expf(m - q.x) + q.y; m = q.x; }
        else         { s += q.y * __expf(q.x - m); }
    }
    __shared__ float shm[256], shs[256];
    shm[t] = m; shs[t] = s;
    __syncthreads();
    for (int o = 128; o > 0; o >>= 1) {
        if (t < o) {
            float m2 = shm[t + o], s2 = shs[t + o];
            if (m2 > shm[t]) { shs[t] = shs[t] * __expf(shm[t] - m2) + s2; shm[t] = m2; }
            else             { shs[t] += s2 * __expf(m2 - shm[t]); }
        }
        __syncthreads();
    }
    if (t == 0)
        g_samp[b] = shm[0] + logf(shs[0]) - ARC_SCALE * g_phi[b];
}

// ---------------- K6: mean over samples -> loss ----------------
__global__ void k_loss(float* __restrict__ out, int B) {
    int t = threadIdx.x;
    float s = 0.f;
    for (int i = t; i < B; i += 256) s += g_samp[i];
    __shared__ float sh[256];
    sh[t] = s;
    __syncthreads();
    for (int o = 128; o > 0; o >>= 1) {
        if (t < o) sh[t] += sh[t + o];
        __syncthreads();
    }
    if (t == 0) out[0] = sh[0] / (float)B;
}

// ---------------- launch ----------------
extern "C" void kernel_launch(void* const* d_in, const int* in_sizes, int n_in,
                              void* d_out, int out_size) {
    const float* emb = (const float*)d_in[0];
    const float* w   = (const float*)d_in[1];
    const void*  gt  = (const void*)d_in[2];
    float*       out = (float*)d_out;

    int B = in_sizes[2];
    int D = in_sizes[0] / B;
    int C = in_sizes[1] / D;
    int nCblk = (C + BN - 1) / BN;

    k_probe<<<1, 256>>>(gt, B, C);
    k_norm_e<<<B, 256>>>(emb, D);
    k_winv<<<(C + 7) / 8, 256>>>(w, C, D);
    k_phi<<<B, 256>>>(w, gt, D, C);
    dim3 grid(nCblk, B / BM);
    k_gemm<<<grid, 256>>>(w, D, C, nCblk);
    k_lse<<<B, 256>>>(nCblk);
    k_loss<<<1, 256>>>(out, B);
}

// round 4
// speedup vs baseline: 2.0519x; 2.0519x over previous
#include <cuda_runtime.h>
#include <cuda_bf16.h>
#include <math.h>
#include <stdint.h>

// ---------------- problem constants ----------------
#define NB 512          // batch
#define ND 512          // embed dim
#define MAX_C 100000
#define CTILE 128       // classes per CTA (M)
#define STILE 64        // samples per inner tile (N)
#define NCBLK_MAX ((MAX_C + CTILE - 1) / CTILE)   // 782
#define NPART_MAX (NCBLK_MAX * 4)                 // 4 partials per CTA (per warp_m)

// ArcFace constants (margin=0.5, scale=64, t=0.2)
#define ARC_COS_M 0.8775825618903728f
#define ARC_SIN_M 0.479425538604203f
#define ARC_TH   (-0.8775825618903728f)
#define ARC_MM    0.2397127693021015f
#define ARC_EPS   1e-7f
#define ARC_SCALE 64.0f

// ---------------- static scratch ----------------
__device__ float          g_en [NB * ND];     // normalized embeddings fp32
__device__ __nv_bfloat16  g_ebf[NB * ND];     // normalized embeddings bf16
__device__ float          g_phi[NB];
__device__ int            g_gt [NB];
__device__ float2         g_part[(size_t)NB * NPART_MAX];
__device__ float          g_samp[NB];
__device__ int            g_gt_is_i32;

// ---------------- PTX helpers (all plain-sm_103-safe) ----------------
__device__ __forceinline__ uint32_t s2u(const void* p) {
    uint32_t a;
    asm("{ .reg .u64 t; cvta.to.shared.u64 t, %1; cvt.u32.u64 %0, t; }" : "=r"(a) : "l"(p));
    return a;
}
#define LDSM_X4(r0, r1, r2, r3, addr)                                          \
    asm volatile("ldmatrix.sync.aligned.m8n8.x4.shared.b16 {%0,%1,%2,%3}, [%4];" \
                 : "=r"(r0), "=r"(r1), "=r"(r2), "=r"(r3) : "r"(addr))
#define LDSM_X2(r0, r1, addr)                                                  \
    asm volatile("ldmatrix.sync.aligned.m8n8.x2.shared.b16 {%0,%1}, [%2];"     \
                 : "=r"(r0), "=r"(r1) : "r"(addr))
__device__ __forceinline__ void mma16816(float* c, const uint32_t* a, const uint32_t* b) {
    asm volatile(
        "mma.sync.aligned.m16n8k16.row.col.f32.bf16.bf16.f32 "
        "{%0,%1,%2,%3}, {%4,%5,%6,%7}, {%8,%9}, {%0,%1,%2,%3};"
        : "+f"(c[0]), "+f"(c[1]), "+f"(c[2]), "+f"(c[3])
        : "r"(a[0]), "r"(a[1]), "r"(a[2]), "r"(a[3]), "r"(b[0]), "r"(b[1]));
}

// ---------------- K0: probe gt dtype (int64 vs int32) ----------------
__global__ void k_probe(const void* __restrict__ gt, int B, int C) {
    const long long* p = (const long long*)gt;
    int t = threadIdx.x;
    int bad = 0;
    for (int i = t; i < B; i += 256) {
        long long v = p[i];
        if (v < 0 || v >= (long long)C) bad = 1;
    }
    __shared__ int sh[256];
    sh[t] = bad; __syncthreads();
    for (int o = 128; o > 0; o >>= 1) { if (t < o) sh[t] |= sh[t + o]; __syncthreads(); }
    if (t == 0) g_gt_is_i32 = sh[0];
}

// ---------------- K1: normalize embedding rows (fp32 + bf16 copies) ----------------
__global__ void k_norm_e(const float* __restrict__ e) {
    int b = blockIdx.x, t = threadIdx.x;
    float ss = 0.f;
    for (int d = t; d < ND; d += 256) { float v = e[(size_t)b * ND + d]; ss += v * v; }
    __shared__ float sh[256];
    sh[t] = ss; __syncthreads();
    for (int o = 128; o > 0; o >>= 1) { if (t < o) sh[t] += sh[t + o]; __syncthreads(); }
    float rn = rsqrtf(sh[0]);
    for (int d = t; d < ND; d += 256) {
        float v = e[(size_t)b * ND + d] * rn;
        g_en [(size_t)b * ND + d] = v;
        g_ebf[(size_t)b * ND + d] = __float2bfloat16(v);
    }
}

// ---------------- K3: per-sample pos/phi (fp32 exact) ----------------
__global__ void k_phi(const float* __restrict__ w, const void* __restrict__ gt, int C) {
    int b = blockIdx.x, t = threadIdx.x;
    __shared__ int sg;
    if (t == 0) {
        long long v;
        if (g_gt_is_i32) v = (long long)((const int*)gt)[b];
        else             v = ((const long long*)gt)[b];
        if (v < 0) v = 0;
        if (v >= C) v = C - 1;
        sg = (int)v;
    }
    __syncthreads();
    int g = sg;
    const float* er = g_en + (size_t)b * ND;
    const float* wr = w + (size_t)g * ND;
    float s = 0.f, q = 0.f;
    for (int d = t; d < ND; d += 256) { float wv = wr[d]; s += er[d] * wv; q += wv * wv; }
    __shared__ float shs[256], shq[256];
    shs[t] = s; shq[t] = q; __syncthreads();
    for (int o = 128; o > 0; o >>= 1) {
        if (t < o) { shs[t] += shs[t + o]; shq[t] += shq[t + o]; }
        __syncthreads();
    }
    if (t == 0) {
        float pos = shs[0] * rsqrtf(shq[0]);
        pos = fminf(fmaxf(pos, -1.f + ARC_EPS), 1.f - ARC_EPS);
        float s2 = fminf(fmaxf(1.f - pos * pos, ARC_EPS), 1.f - ARC_EPS);
        float ph = pos * ARC_COS_M - sqrtf(s2) * ARC_SIN_M;
        if (!(pos > ARC_TH)) ph = pos - ARC_MM;
        g_phi[b] = ph;
        g_gt[b] = g;
    }
}

// ---------------- K4: HMMA GEMM + margin + partial LSE ----------------
// SMEM: W bf16 [128 cls][512 k] (128KB, swizzled) + E bf16 [64 smp][512 k]
//       (64KB, swizzled) + winv[128] + phi[64] + gt[64]
#define SM_W 0
#define SM_E (CTILE * ND * 2)                  // 131072
#define SM_WINV (SM_E + STILE * ND * 2)        // 196608
#define SM_PHI  (SM_WINV + CTILE * 4)          // 197120
#define SM_GT   (SM_PHI + STILE * 4)           // 197376
#define SMEM_NEED (SM_GT + STILE * 4 + 256)    // ~197.9KB

// row-of-1024B swizzle: XOR byte bits[6:4] with (row & 7)
__device__ __forceinline__ uint32_t swz(uint32_t row, uint32_t koffBytes) {
    return row * 1024u + (koffBytes ^ ((row & 7u) << 4));
}

__device__ __forceinline__ void lse_merge(float& m, float& s, float m2, float s2) {
    if (m2 > m) { s = s * __expf(m - m2) + s2; m = m2; }
    else        { s += s2 * __expf(m2 - m); }
}

__global__ __launch_bounds__(256, 1) void k_gemm(const float* __restrict__ w,
                                                 int B, int C, int npart) {
    extern __shared__ char smp[];
    const uint32_t sb = s2u(smp);
    float* winv_sm = (float*)(smp + SM_WINV);
    float* phi_sm  = (float*)(smp + SM_PHI);
    int*   gt_sm   = (int*)  (smp + SM_GT);

    const int t    = threadIdx.x;
    const int wid  = t >> 5;
    const int lane = t & 31;
    const int warp_m = wid >> 1;   // 0..3 : 32 classes each
    const int warp_n = wid & 1;    // 0..1 : 32 samples each
    const int cn0  = blockIdx.x * CTILE;

    // ---- Phase 1: W tile fp32 -> bf16 SMEM, fused sum-of-squares ----
    {
        const int clsLoc = t >> 1;          // 0..127
        const int half   = t & 1;           // k-half
        const int clsG   = cn0 + clsLoc;
        const float* wr = w + (size_t)clsG * ND + half * 256;
        float ssq = 0.f;
        #pragma unroll 8
        for (int i = 0; i < 64; i++) {
            float4 v = make_float4(0.f, 0.f, 0.f, 0.f);
            if (clsG < C) v = *(const float4*)(wr + i * 4);
            ssq += v.x * v.x + v.y * v.y + v.z * v.z + v.w * v.w;
            __nv_bfloat162 lo = __float22bfloat162_rn(make_float2(v.x, v.y));
            __nv_bfloat162 hi = __float22bfloat162_rn(make_float2(v.z, v.w));
            uint2 pk;
            pk.x = *(uint32_t*)&lo;
            pk.y = *(uint32_t*)&hi;
            uint32_t k = (uint32_t)(half * 256 + i * 4);
            *(uint2*)(smp + SM_W + swz(clsLoc, k * 2)) = pk;
        }
        ssq += __shfl_xor_sync(0xffffffffu, ssq, 1);
        if (half == 0) winv_sm[clsLoc] = rsqrtf(ssq);
    }
    __syncthreads();

    // ---- per-lane ldmatrix address components (loop-invariant) ----
    // A frags: classes (row-major m16 x k16), non-trans x4
    uint32_t aRow[2];
    #pragma unroll
    for (int mi = 0; mi < 2; mi++) {
        uint32_t r = (uint32_t)(warp_m * 32 + mi * 16 + (lane & 15));
        aRow[mi] = sb + SM_W + r * 1024u;
    }
    const uint32_t swA   = (uint32_t)((lane & 7) << 4);
    const uint32_t kOffA = (uint32_t)((lane >> 4) << 3);
    // B frags: samples (col-major k16 x n8 == stored [sample][k]), non-trans x2
    uint32_t bRow[4];
    #pragma unroll
    for (int ni = 0; ni < 4; ni++) {
        uint32_t r = (uint32_t)(warp_n * 32 + ni * 8 + (lane & 7));
        bRow[ni] = sb + SM_E + r * 1024u;
    }
    const uint32_t swB   = swA;
    const uint32_t kOffB = (uint32_t)(((lane >> 3) & 1) << 3);

    const float HI = 1.f - ARC_EPS, LO = -1.f + ARC_EPS;
    const int nTiles = B / STILE;

    for (int st = 0; st < nTiles; st++) {
        const int s0 = st * STILE;
        __syncthreads();   // previous k-loop/epilogue done before E overwrite

        // ---- load E tile: 64 samples x 512 k bf16 (swizzled) ----
        {
            const int srow = t >> 2;          // 0..63
            const int ch   = t & 3;
            const uint4* src = (const uint4*)(g_ebf + (size_t)(s0 + srow) * ND);
            #pragma unroll 4
            for (int i = 0; i < 16; i++) {
                int idx16 = ch * 16 + i;      // 0..63 (16B units)
                uint4 v = src[idx16];
                *(uint4*)(smp + SM_E + swz((uint32_t)srow, (uint32_t)(idx16 * 16))) = v;
            }
            if (t < STILE) {
                phi_sm[t] = g_phi[s0 + t];
                gt_sm[t]  = g_gt[s0 + t];
            }
        }
        __syncthreads();

        // ---- k-loop: pure LDSM + HMMA ----
        float acc[2][4][4];
        #pragma unroll
        for (int mi = 0; mi < 2; mi++)
            #pragma unroll
            for (int ni = 0; ni < 4; ni++)
                #pragma unroll
                for (int q = 0; q < 4; q++) acc[mi][ni][q] = 0.f;

        #pragma unroll 4
        for (int k0 = 0; k0 < ND; k0 += 16) {
            uint32_t offA = (((uint32_t)k0 + kOffA) << 1) ^ swA;
            uint32_t offB = (((uint32_t)k0 + kOffB) << 1) ^ swB;
            uint32_t a[2][4], b[4][2];
            #pragma unroll
            for (int mi = 0; mi < 2; mi++)
                LDSM_X4(a[mi][0], a[mi][1], a[mi][2], a[mi][3], aRow[mi] + offA);
            #pragma unroll
            for (int ni = 0; ni < 4; ni++)
                LDSM_X2(b[ni][0], b[ni][1], bRow[ni] + offB);
            #pragma unroll
            for (int mi = 0; mi < 2; mi++)
                #pragma unroll
                for (int ni = 0; ni < 4; ni++)
                    mma16816(acc[mi][ni], a[mi], b[ni]);
        }

        // ---- epilogue: margin transform + online LSE over this warp's 32 classes ----
        // acc layout: rows (classes) r = lane>>2 and +8; cols (samples) 2*(lane&3)+i
        #pragma unroll
        for (int ni = 0; ni < 4; ni++) {
            #pragma unroll
            for (int i = 0; i < 2; i++) {
                const int sLoc = warp_n * 32 + ni * 8 + 2 * (lane & 3) + i;
                const float ph = phi_sm[sLoc];
                const int   gi = gt_sm[sLoc];
                float m = -3.0e38f, sum = 0.f;
                #pragma unroll
                for (int mi = 0; mi < 2; mi++) {
                    #pragma unroll
                    for (int rh = 0; rh < 2; rh++) {
                        const int clsLoc = warp_m * 32 + mi * 16 + (lane >> 2) + rh * 8;
                        const int c = cn0 + clsLoc;
                        if (c < C) {
                            float cv = acc[mi][ni][rh * 2 + i] * winv_sm[clsLoc];
                            cv = fminf(fmaxf(cv, LO), HI);
                            float v = (cv > ph) ? fmaf(1.2f, cv, 0.2f) : cv;
                            if (c == gi) v = ph;
                            v *= ARC_SCALE;
                            if (v <= m) sum += __expf(v - m);
                            else { sum = fmaf(sum, __expf(m - v), 1.f); m = v; }
                        }
                    }
                }
                // reduce across the 8 lanes holding this sample (lane>>2 = 0..7)
                #pragma unroll
                for (int o = 4; o < 32; o <<= 1) {
                    float m2 = __shfl_xor_sync(0xffffffffu, m, o);
                    float s2 = __shfl_xor_sync(0xffffffffu, sum, o);
                    lse_merge(m, sum, m2, s2);
                }
                if ((lane >> 2) == 0)
                    g_part[(size_t)(s0 + sLoc) * npart + blockIdx.x * 4 + warp_m] =
                        make_float2(m, sum);
            }
        }
    }
}

// ---------------- K5: per-sample logsumexp combine ----------------
__global__ void k_lse(int npart) {
    int b = blockIdx.x, t = threadIdx.x;
    const float2* p = g_part + (size_t)b * npart;
    float m = -3.0e38f, s = 0.f;
    for (int i = t; i < npart; i += 256) {
        float2 q = p[i];
        lse_merge(m, s, q.x, q.y);
    }
    __shared__ float shm[256], shs[256];
    shm[t] = m; shs[t] = s; __syncthreads();
    for (int o = 128; o > 0; o >>= 1) {
        if (t < o) {
            float m2 = shm[t + o], s2 = shs[t + o];
            if (m2 > shm[t]) { shs[t] = shs[t] * __expf(shm[t] - m2) + s2; shm[t] = m2; }
            else             { shs[t] += s2 * __expf(m2 - shm[t]); }
        }
        __syncthreads();
    }
    if (t == 0) g_samp[b] = shm[0] + logf(shs[0]) - ARC_SCALE * g_phi[b];
}

// ---------------- K6: mean -> loss ----------------
__global__ void k_loss(float* __restrict__ out, int B) {
    int t = threadIdx.x;
    float s = 0.f;
    for (int i = t; i < B; i += 256) s += g_samp[i];
    __shared__ float sh[256];
    sh[t] = s; __syncthreads();
    for (int o = 128; o > 0; o >>= 1) { if (t < o) sh[t] += sh[t + o]; __syncthreads(); }
    if (t == 0) out[0] = sh[0] / (float)B;
}

// ---------------- launch ----------------
extern "C" void kernel_launch(void* const* d_in, const int* in_sizes, int n_in,
                              void* d_out, int out_size) {
    const float* emb = (const float*)d_in[0];
    const float* w   = (const float*)d_in[1];
    const void*  gt  = (const void*)d_in[2];
    float*       out = (float*)d_out;

    int B = in_sizes[2];
    int D = in_sizes[0] / B;     // 512
    int C = in_sizes[1] / D;     // 100000
    int nCblk = (C + CTILE - 1) / CTILE;
    int npart = nCblk * 4;

    static int smem_set = 0;
    if (!smem_set) {
        cudaFuncSetAttribute(k_gemm, cudaFuncAttributeMaxDynamicSharedMemorySize, SMEM_NEED);
        smem_set = 1;
    }

    k_probe<<<1, 256>>>(gt, B, C);
    k_norm_e<<<B, 256>>>(emb);
    k_phi<<<B, 256>>>(w, gt, C);
    k_gemm<<<nCblk, 256, SMEM_NEED>>>(w, B, C, npart);
    k_lse<<<B, 256>>>(npart);
    k_loss<<<1, 256>>>(out, B);
}